// round 8
// baseline (speedup 1.0000x reference)
#include <cuda_runtime.h>

#define D_   24
#define F_   48           // NK*D
#define H_   64
#define DEG_ 32
#define NW   8            // warps per block
#define NPW  8            // nodes per warp (sequential rounds)
#define NPB  (NW * NPW)   // 64 nodes per block
#define TPB  (NW * 32)    // 256 threads
#define FDS  20           // featD j-stride in floats (16 data + 4 pad; keeps 16B alignment)
#define NMAX 100000

// Padded feature table: 128B per row (24 data + 8 zero floats)
__device__ __align__(16) float g_xpad[(size_t)NMAX * 32];

typedef unsigned long long u64;

__device__ __forceinline__ u64 pack2(float lo, float hi) {
    u64 r; asm("mov.b64 %0, {%1, %2};" : "=l"(r) : "f"(lo), "f"(hi)); return r;
}
__device__ __forceinline__ void unpack2(float& lo, float& hi, u64 v) {
    asm("mov.b64 {%0, %1}, %2;" : "=f"(lo), "=f"(hi) : "l"(v));
}
__device__ __forceinline__ u64 ffma2(u64 a, u64 b, u64 c) {
    u64 d; asm("fma.rn.f32x2 %0, %1, %2, %3;" : "=l"(d) : "l"(a), "l"(b), "l"(c)); return d;
}
__device__ __forceinline__ u64 fadd2(u64 a, u64 b) {
    u64 d; asm("add.rn.f32x2 %0, %1, %2;" : "=l"(d) : "l"(a), "l"(b)); return d;
}

// Fully scalar pad: no assumptions about input pointer alignment.
__global__ __launch_bounds__(256) void pad_x_kernel(const float* __restrict__ x, int N) {
    int t = blockIdx.x * blockDim.x + threadIdx.x;   // N*32 threads, one float each
    if (t >= N * 32) return;
    const int row = t >> 5, c = t & 31;
    g_xpad[t] = (c < D_) ? __ldg(x + row * D_ + c) : 0.f;
}

__global__ __launch_bounds__(TPB) void gnn_fused_kernel(
    const int* __restrict__ edge_idx,   // [2, E] int32; src = first E
    const float* __restrict__ kvals,    // [2, E]
    const float* __restrict__ W,        // [64, 48] row-major
    float* __restrict__ out,            // [N, 64]
    int N, int E)
{
    __shared__ __align__(16) float2 WtP[F_ * 32];        // 12 KB: (W[2l][j], W[2l+1][j])
    __shared__ __align__(16) float  featD[NW][F_ * FDS]; // 30 KB: featD[w][j*20+2g] dup
    __shared__ __align__(16) int    soff[NW][DEG_];      // 1 KB  (src*128 byte offsets)
    __shared__ __align__(16) float  sk0[NW][DEG_];       // 1 KB
    __shared__ __align__(16) float  sk1[NW][DEG_];       // 1 KB

    const int tid  = threadIdx.x;
    const int w    = tid >> 5;
    const int lane = tid & 31;

    // Stage W packed-pairs (3072 elements, scalar loads from W)
    for (int idx = tid; idx < F_ * 32; idx += TPB) {
        const int j = idx >> 5, l = idx & 31;
        WtP[idx] = make_float2(W[(2 * l) * F_ + j], W[(2 * l + 1) * F_ + j]);
    }

    const int  base  = blockIdx.x * NPB + w * NPW;
    const char* xlane = (const char*)(g_xpad + lane);

    // ---- Gather: 8 sequential nodes per warp ----
    #pragma unroll 1
    for (int r = 0; r < NPW; ++r) {
        const int  node  = base + r;
        const bool valid = node < N;
        if (valid) {
            const int e = node * DEG_ + lane;
            soff[w][lane] = edge_idx[e] << 7;       // *128
            sk0[w][lane]  = kvals[e];
            sk1[w][lane]  = kvals[e + E];
        } else {
            // Tail block: keep staging defined so the branchless gather below
            // reads a safe in-bounds offset (node 0) instead of garbage.
            soff[w][lane] = 0;
            sk0[w][lane]  = 0.f;
            sk1[w][lane]  = 0.f;
        }
        __syncwarp();

        const float xi = valid ? __ldg((const float*)(xlane + ((long long)node << 7))) : 0.f;
        u64 acc0p = 0, acc1p = 0, sumxp = 0;       // packed (even, odd) edge accumulators

        #pragma unroll
        for (int c = 0; c < 4; ++c) {
            const int4 oa = *(const int4*)&soff[w][c * 8];
            const int4 ob = *(const int4*)&soff[w][c * 8 + 4];
            float xv[8];
            xv[0] = __ldg((const float*)(xlane + oa.x));
            xv[1] = __ldg((const float*)(xlane + oa.y));
            xv[2] = __ldg((const float*)(xlane + oa.z));
            xv[3] = __ldg((const float*)(xlane + oa.w));
            xv[4] = __ldg((const float*)(xlane + ob.x));
            xv[5] = __ldg((const float*)(xlane + ob.y));
            xv[6] = __ldg((const float*)(xlane + ob.z));
            xv[7] = __ldg((const float*)(xlane + ob.w));

            const longlong2 k0q = *(const longlong2*)&sk0[w][c * 8];  // (k0 e0,e1)(e2,e3)
            const longlong2 k0r = *(const longlong2*)&sk0[w][c * 8 + 4];
            const longlong2 k1q = *(const longlong2*)&sk1[w][c * 8];
            const longlong2 k1r = *(const longlong2*)&sk1[w][c * 8 + 4];

            const u64 xp0 = pack2(xv[0], xv[1]);
            const u64 xp1 = pack2(xv[2], xv[3]);
            const u64 xp2 = pack2(xv[4], xv[5]);
            const u64 xp3 = pack2(xv[6], xv[7]);

            acc0p = ffma2((u64)k0q.x, xp0, acc0p);
            acc0p = ffma2((u64)k0q.y, xp1, acc0p);
            acc0p = ffma2((u64)k0r.x, xp2, acc0p);
            acc0p = ffma2((u64)k0r.y, xp3, acc0p);
            acc1p = ffma2((u64)k1q.x, xp0, acc1p);
            acc1p = ffma2((u64)k1q.y, xp1, acc1p);
            acc1p = ffma2((u64)k1r.x, xp2, acc1p);
            acc1p = ffma2((u64)k1r.y, xp3, acc1p);
            sumxp = fadd2(sumxp, xp0);
            sumxp = fadd2(sumxp, xp1);
            sumxp = fadd2(sumxp, xp2);
            sumxp = fadd2(sumxp, xp3);
        }

        float a0l, a0h, a1l, a1h, sxl, sxh;
        unpack2(a0l, a0h, acc0p);
        unpack2(a1l, a1h, acc1p);
        unpack2(sxl, sxh, sumxp);
        const float m  = (sxl + sxh) * (1.0f / DEG_);
        const float v0 = (a0l + a0h) - m + xi;
        const float v1 = (a1l + a1h) - m + xi;

        if (lane < D_) {   // feature j=lane and j=lane+24, duplicated for packed epilogue
            *(u64*)&featD[w][lane * FDS + 2 * r]        = pack2(v0, v0);
            *(u64*)&featD[w][(lane + D_) * FDS + 2 * r] = pack2(v1, v1);
        }
        __syncwarp();   // protect staging buffers before next round
    }

    __syncthreads();    // WtP visible

    // ---- Epilogue: one W pass serves 8 nodes; all math packed f32x2 ----
    u64 yp[NPW];
    #pragma unroll
    for (int g = 0; g < NPW; ++g) yp[g] = 0;

    #pragma unroll
    for (int j = 0; j < F_; ++j) {
        const u64 wp = *(const u64*)&WtP[j * 32 + lane];        // (W[2l][j], W[2l+1][j])
        const longlong2 fa = *(const longlong2*)&featD[w][j * FDS];       // (f0,f0)(f1,f1)
        const longlong2 fb = *(const longlong2*)&featD[w][j * FDS + 4];   // (f2,f2)(f3,f3)
        const longlong2 fc = *(const longlong2*)&featD[w][j * FDS + 8];
        const longlong2 fd = *(const longlong2*)&featD[w][j * FDS + 12];
        yp[0] = ffma2(wp, (u64)fa.x, yp[0]);
        yp[1] = ffma2(wp, (u64)fa.y, yp[1]);
        yp[2] = ffma2(wp, (u64)fb.x, yp[2]);
        yp[3] = ffma2(wp, (u64)fb.y, yp[3]);
        yp[4] = ffma2(wp, (u64)fc.x, yp[4]);
        yp[5] = ffma2(wp, (u64)fc.y, yp[5]);
        yp[6] = ffma2(wp, (u64)fd.x, yp[6]);
        yp[7] = ffma2(wp, (u64)fd.y, yp[7]);
    }

    #pragma unroll
    for (int g = 0; g < NPW; ++g) {
        const int node = base + g;
        if (node < N)    // channels (2l, 2l+1) adjacent -> one 8B store
            *(u64*)(out + (long long)node * H_ + 2 * lane) = yp[g];
    }
}

extern "C" void kernel_launch(void* const* d_in, const int* in_sizes, int n_in,
                              void* d_out, int out_size) {
    const float* x    = (const float*)d_in[0];      // [N, 24]
    const int*   eidx = (const int*)d_in[1];        // [2, E] int32
    const float* kv   = (const float*)d_in[2];      // [2, E]
    const float* W    = (const float*)d_in[3];      // [64, 48]
    float*       out  = (float*)d_out;

    const int N = in_sizes[0] / D_;
    const int E = in_sizes[2] / 2;

    pad_x_kernel<<<(N * 32 + 255) / 256, 256>>>(x, N);
    gnn_fused_kernel<<<(N + NPB - 1) / NPB, TPB>>>(eidx, kv, W, out, N, E);
}

// round 9
// speedup vs baseline: 1.4042x; 1.4042x over previous
#include <cuda_runtime.h>

#define D_   24
#define F_   48           // NK*D
#define H_   64
#define DEG_ 32
#define NW   8            // warps per block
#define NPW  8            // nodes per warp (sequential rounds)
#define NPB  (NW * NPW)   // 64 nodes per block
#define TPB  (NW * 32)    // 256 threads
#define FS   12           // featW g-stride
#define WS   65           // Wt h-stride (conflict-free transpose store + read)

__global__ __launch_bounds__(TPB, 4) void gnn_fused_kernel(
    const float* __restrict__ x,        // [N, 24]
    const int* __restrict__ edge_idx,   // [2, E] int32; src = first E
    const float* __restrict__ kvals,    // [2, E]
    const float* __restrict__ W,        // [64, 48] row-major
    float* __restrict__ out,            // [N, 64]
    int N, int E)
{
    __shared__ float  Wt[F_ * WS];            // 12.2 KB, Wt[j*65+h] = W[h][j]
    __shared__ float  featW[NW][F_ * FS];     // 18 KB, warp-private featW[w][j*12+g]
    __shared__ int    soff[NW][DEG_];         // 1 KB  (src*96 byte offsets)
    __shared__ float2 skk[NW][DEG_];          // 2 KB  (k0,k1 per edge)

    const int tid  = threadIdx.x;
    const int w    = tid >> 5;
    const int lane = tid & 31;

    // Stage W transposed (coalesced LDG, conflict-free STS via stride-65)
    for (int idx = tid; idx < H_ * F_; idx += TPB) {
        const int h = idx / F_, j = idx - h * F_;
        Wt[j * WS + h] = W[idx];
    }

    const int  base  = blockIdx.x * NPB + w * NPW;
    const bool pred  = lane < D_;
    const char* xlane = (const char*)(x + lane);

    // ---- Prefetch round 0 staging into registers ----
    int off_n = 0; float k0_n = 0.f, k1_n = 0.f;
    {
        const bool v0 = base < N;
        const int  e0 = base * DEG_ + lane;
        if (v0) {
            off_n = edge_idx[e0] * 96;
            k0_n  = kvals[e0];
            k1_n  = kvals[e0 + E];
        }
    }

    // ---- Gather: 8 sequential nodes per warp, staging pipelined ----
    #pragma unroll 1
    for (int r = 0; r < NPW; ++r) {
        const int  node  = base + r;
        const bool valid = node < N;

        // Publish this round's staging (registers -> smem)
        soff[w][lane] = off_n;
        skk[w][lane]  = make_float2(k0_n, k1_n);
        __syncwarp();

        // Prefetch NEXT round's staging (independent LDGs overlap the gather)
        if (r + 1 < NPW) {
            const int  n2 = node + 1;
            const bool v2 = n2 < N;
            const int  e2 = n2 * DEG_ + lane;
            off_n = 0; k0_n = 0.f; k1_n = 0.f;
            if (v2) {
                off_n = edge_idx[e2] * 96;
                k0_n  = kvals[e2];
                k1_n  = kvals[e2 + E];
            }
        }

        const bool act = pred && valid;
        const float xi = act ? x[node * D_ + lane] : 0.f;
        float acc0 = 0.f, acc1 = 0.f, sumx = 0.f;

        #pragma unroll
        for (int c = 0; c < 4; ++c) {
            const int4 oa = *(const int4*)&soff[w][c * 8];
            const int4 ob = *(const int4*)&soff[w][c * 8 + 4];
            float xv[8];
            xv[0] = act ? __ldg((const float*)(xlane + oa.x)) : 0.f;
            xv[1] = act ? __ldg((const float*)(xlane + oa.y)) : 0.f;
            xv[2] = act ? __ldg((const float*)(xlane + oa.z)) : 0.f;
            xv[3] = act ? __ldg((const float*)(xlane + oa.w)) : 0.f;
            xv[4] = act ? __ldg((const float*)(xlane + ob.x)) : 0.f;
            xv[5] = act ? __ldg((const float*)(xlane + ob.y)) : 0.f;
            xv[6] = act ? __ldg((const float*)(xlane + ob.z)) : 0.f;
            xv[7] = act ? __ldg((const float*)(xlane + ob.w)) : 0.f;

            const float4 kA = *(const float4*)&skk[w][c * 8];      // edges 0,1
            const float4 kB = *(const float4*)&skk[w][c * 8 + 2];  // edges 2,3
            const float4 kC = *(const float4*)&skk[w][c * 8 + 4];  // edges 4,5
            const float4 kD = *(const float4*)&skk[w][c * 8 + 6];  // edges 6,7

            acc0 = fmaf(kA.x, xv[0], acc0); acc1 = fmaf(kA.y, xv[0], acc1); sumx += xv[0];
            acc0 = fmaf(kA.z, xv[1], acc0); acc1 = fmaf(kA.w, xv[1], acc1); sumx += xv[1];
            acc0 = fmaf(kB.x, xv[2], acc0); acc1 = fmaf(kB.y, xv[2], acc1); sumx += xv[2];
            acc0 = fmaf(kB.z, xv[3], acc0); acc1 = fmaf(kB.w, xv[3], acc1); sumx += xv[3];
            acc0 = fmaf(kC.x, xv[4], acc0); acc1 = fmaf(kC.y, xv[4], acc1); sumx += xv[4];
            acc0 = fmaf(kC.z, xv[5], acc0); acc1 = fmaf(kC.w, xv[5], acc1); sumx += xv[5];
            acc0 = fmaf(kD.x, xv[6], acc0); acc1 = fmaf(kD.y, xv[6], acc1); sumx += xv[6];
            acc0 = fmaf(kD.z, xv[7], acc0); acc1 = fmaf(kD.w, xv[7], acc1); sumx += xv[7];
        }

        if (pred) {
            const float m = sumx * (1.0f / DEG_);
            featW[w][lane * FS + r]        = acc0 - m + xi;   // feature j=lane
            featW[w][(lane + D_) * FS + r] = acc1 - m + xi;   // feature j=lane+24
        }
        __syncwarp();   // protect soff/skk before next round publishes
    }

    __syncthreads();    // Wt visible to all warps

    // ---- Epilogue: one W pass serves 8 nodes per warp ----
    float y0[NPW], y1[NPW];
    #pragma unroll
    for (int g = 0; g < NPW; ++g) { y0[g] = 0.f; y1[g] = 0.f; }

    #pragma unroll
    for (int j = 0; j < F_; ++j) {
        const float w0 = Wt[j * WS + lane];        // conflict-free
        const float w1 = Wt[j * WS + lane + 32];
        const float4 fa = *(const float4*)&featW[w][j * FS];      // broadcast g=0..3
        const float4 fb = *(const float4*)&featW[w][j * FS + 4];  // broadcast g=4..7
        y0[0] = fmaf(fa.x, w0, y0[0]); y1[0] = fmaf(fa.x, w1, y1[0]);
        y0[1] = fmaf(fa.y, w0, y0[1]); y1[1] = fmaf(fa.y, w1, y1[1]);
        y0[2] = fmaf(fa.z, w0, y0[2]); y1[2] = fmaf(fa.z, w1, y1[2]);
        y0[3] = fmaf(fa.w, w0, y0[3]); y1[3] = fmaf(fa.w, w1, y1[3]);
        y0[4] = fmaf(fb.x, w0, y0[4]); y1[4] = fmaf(fb.x, w1, y1[4]);
        y0[5] = fmaf(fb.y, w0, y0[5]); y1[5] = fmaf(fb.y, w1, y1[5]);
        y0[6] = fmaf(fb.z, w0, y0[6]); y1[6] = fmaf(fb.z, w1, y1[6]);
        y0[7] = fmaf(fb.w, w0, y0[7]); y1[7] = fmaf(fb.w, w1, y1[7]);
    }

    #pragma unroll
    for (int g = 0; g < NPW; ++g) {
        const int node = base + g;
        if (node < N) {
            out[node * H_ + lane]      = y0[g];
            out[node * H_ + lane + 32] = y1[g];
        }
    }
}

extern "C" void kernel_launch(void* const* d_in, const int* in_sizes, int n_in,
                              void* d_out, int out_size) {
    const float* x    = (const float*)d_in[0];      // [N, 24]
    const int*   eidx = (const int*)d_in[1];        // [2, E] int32
    const float* kv   = (const float*)d_in[2];      // [2, E]
    const float* W    = (const float*)d_in[3];      // [64, 48]
    float*       out  = (float*)d_out;

    const int N = in_sizes[0] / D_;
    const int E = in_sizes[2] / 2;

    const int blocks = (N + NPB - 1) / NPB;
    gnn_fused_kernel<<<blocks, TPB>>>(x, eidx, kv, W, out, N, E);
}

// round 10
// speedup vs baseline: 1.4491x; 1.0320x over previous
#include <cuda_runtime.h>

#define D_   24
#define F_   48           // NK*D
#define H_   64
#define DEG_ 32
#define NW   8            // warps per block
#define NPW  8            // nodes per warp (sequential rounds)
#define NPB  (NW * NPW)   // 64 nodes per block
#define TPB  (NW * 32)    // 256 threads
#define FS   12           // featW g-stride (float4-aligned reads)
#define WS   65           // Wt h-stride (conflict-free transpose store + read)

typedef unsigned long long u64;

__device__ __forceinline__ u64 pack2(float lo, float hi) {
    u64 r; asm("mov.b64 %0, {%1, %2};" : "=l"(r) : "f"(lo), "f"(hi)); return r;
}
__device__ __forceinline__ void unpack2(float& lo, float& hi, u64 v) {
    asm("mov.b64 {%0, %1}, %2;" : "=f"(lo), "=f"(hi) : "l"(v));
}
__device__ __forceinline__ u64 ffma2(u64 a, u64 b, u64 c) {
    u64 d; asm("fma.rn.f32x2 %0, %1, %2, %3;" : "=l"(d) : "l"(a), "l"(b), "l"(c)); return d;
}

__global__ __launch_bounds__(TPB, 4) void gnn_fused_kernel(
    const float* __restrict__ x,        // [N, 24]
    const int* __restrict__ edge_idx,   // [2, E] int32; src = first E
    const float* __restrict__ kvals,    // [2, E]
    const float* __restrict__ W,        // [64, 48] row-major
    float* __restrict__ out,            // [N, 64]
    int N, int E)
{
    __shared__ float Wt[F_ * WS];                      // 12.2 KB, Wt[j*65+h]=W[h][j]
    __shared__ float featW[NW][F_ * FS];               // 18 KB
    __shared__ __align__(16) int   soff[NW][DEG_];     // 1 KB (src*96 byte offsets)
    __shared__ __align__(16) float sk0[NW][DEG_];      // 1 KB (k0 - 1/32)
    __shared__ __align__(16) float sk1[NW][DEG_];      // 1 KB (k1 - 1/32)

    const int tid  = threadIdx.x;
    const int w    = tid >> 5;
    const int lane = tid & 31;

    // Stage W transposed (coalesced LDG, conflict-free STS via stride-65)
    for (int idx = tid; idx < H_ * F_; idx += TPB) {
        const int h = idx / F_, j = idx - h * F_;
        Wt[j * WS + h] = W[idx];
    }

    const int  base  = blockIdx.x * NPB + w * NPW;
    const bool pred  = lane < D_;
    const char* xlane = (const char*)(x + lane);

    // ---- Prefetch round 0 staging (k' = k - 1/32 folds the neighbor mean) ----
    int off_n = 0; float k0_n = 0.f, k1_n = 0.f;
    if (base < N) {
        const int e0 = base * DEG_ + lane;
        off_n = edge_idx[e0] * 96;
        k0_n  = kvals[e0]     - 0.03125f;
        k1_n  = kvals[e0 + E] - 0.03125f;
    }

    // ---- Gather: 8 sequential nodes per warp, staging pipelined ----
    #pragma unroll 1
    for (int r = 0; r < NPW; ++r) {
        const int  node  = base + r;
        const bool valid = node < N;

        soff[w][lane] = off_n;
        sk0[w][lane]  = k0_n;
        sk1[w][lane]  = k1_n;
        __syncwarp();

        if (r + 1 < NPW) {          // prefetch next round (overlaps gathers)
            const int n2 = node + 1;
            off_n = 0; k0_n = 0.f; k1_n = 0.f;
            if (n2 < N) {
                const int e2 = n2 * DEG_ + lane;
                off_n = edge_idx[e2] * 96;
                k0_n  = kvals[e2]     - 0.03125f;
                k1_n  = kvals[e2 + E] - 0.03125f;
            }
        }

        const bool act = pred && valid;
        const float xi = act ? x[node * D_ + lane] : 0.f;
        u64 acc0p = 0, acc1p = 0;   // (even-edge sum, odd-edge sum) packed

        #pragma unroll
        for (int c = 0; c < 4; ++c) {
            const int4 oa = *(const int4*)&soff[w][c * 8];
            const int4 ob = *(const int4*)&soff[w][c * 8 + 4];
            float xv[8];
            xv[0] = act ? __ldg((const float*)(xlane + oa.x)) : 0.f;
            xv[1] = act ? __ldg((const float*)(xlane + oa.y)) : 0.f;
            xv[2] = act ? __ldg((const float*)(xlane + oa.z)) : 0.f;
            xv[3] = act ? __ldg((const float*)(xlane + oa.w)) : 0.f;
            xv[4] = act ? __ldg((const float*)(xlane + ob.x)) : 0.f;
            xv[5] = act ? __ldg((const float*)(xlane + ob.y)) : 0.f;
            xv[6] = act ? __ldg((const float*)(xlane + ob.z)) : 0.f;
            xv[7] = act ? __ldg((const float*)(xlane + ob.w)) : 0.f;

            // k' pairs come packed straight from smem (broadcast LDS.128)
            const longlong2 k0q = *(const longlong2*)&sk0[w][c * 8];      // e(0,1),(2,3)
            const longlong2 k0r = *(const longlong2*)&sk0[w][c * 8 + 4];  // e(4,5),(6,7)
            const longlong2 k1q = *(const longlong2*)&sk1[w][c * 8];
            const longlong2 k1r = *(const longlong2*)&sk1[w][c * 8 + 4];

            const u64 xp0 = pack2(xv[0], xv[1]);
            const u64 xp1 = pack2(xv[2], xv[3]);
            const u64 xp2 = pack2(xv[4], xv[5]);
            const u64 xp3 = pack2(xv[6], xv[7]);

            acc0p = ffma2((u64)k0q.x, xp0, acc0p);
            acc0p = ffma2((u64)k0q.y, xp1, acc0p);
            acc0p = ffma2((u64)k0r.x, xp2, acc0p);
            acc0p = ffma2((u64)k0r.y, xp3, acc0p);
            acc1p = ffma2((u64)k1q.x, xp0, acc1p);
            acc1p = ffma2((u64)k1q.y, xp1, acc1p);
            acc1p = ffma2((u64)k1r.x, xp2, acc1p);
            acc1p = ffma2((u64)k1r.y, xp3, acc1p);
        }

        if (pred) {
            float a0l, a0h, a1l, a1h;
            unpack2(a0l, a0h, acc0p);
            unpack2(a1l, a1h, acc1p);
            featW[w][lane * FS + r]        = a0l + a0h + xi;   // feature j=lane
            featW[w][(lane + D_) * FS + r] = a1l + a1h + xi;   // feature j=lane+24
        }
        __syncwarp();
    }

    __syncthreads();    // Wt visible to all warps

    // ---- Epilogue: one W pass serves 8 nodes; node-pairs packed f32x2 ----
    u64 yA[4], yB[4];   // yA[p] = (y_ch(lane) node 2p, node 2p+1); yB = ch lane+32
    #pragma unroll
    for (int p = 0; p < 4; ++p) { yA[p] = 0; yB[p] = 0; }

    #pragma unroll
    for (int j = 0; j < F_; ++j) {
        const float w0 = Wt[j * WS + lane];        // conflict-free
        const float w1 = Wt[j * WS + lane + 32];
        const u64 w0p = pack2(w0, w0);
        const u64 w1p = pack2(w1, w1);
        const longlong2 fa = *(const longlong2*)&featW[w][j * FS];      // (f0,f1)(f2,f3)
        const longlong2 fb = *(const longlong2*)&featW[w][j * FS + 4];  // (f4,f5)(f6,f7)
        yA[0] = ffma2(w0p, (u64)fa.x, yA[0]);
        yA[1] = ffma2(w0p, (u64)fa.y, yA[1]);
        yA[2] = ffma2(w0p, (u64)fb.x, yA[2]);
        yA[3] = ffma2(w0p, (u64)fb.y, yA[3]);
        yB[0] = ffma2(w1p, (u64)fa.x, yB[0]);
        yB[1] = ffma2(w1p, (u64)fa.y, yB[1]);
        yB[2] = ffma2(w1p, (u64)fb.x, yB[2]);
        yB[3] = ffma2(w1p, (u64)fb.y, yB[3]);
    }

    #pragma unroll
    for (int p = 0; p < 4; ++p) {
        const int n0 = base + 2 * p, n1 = n0 + 1;
        float aLo, aHi, bLo, bHi;
        unpack2(aLo, aHi, yA[p]);
        unpack2(bLo, bHi, yB[p]);
        if (n0 < N) {
            out[n0 * H_ + lane]      = aLo;
            out[n0 * H_ + lane + 32] = bLo;
        }
        if (n1 < N) {
            out[n1 * H_ + lane]      = aHi;
            out[n1 * H_ + lane + 32] = bHi;
        }
    }
}

extern "C" void kernel_launch(void* const* d_in, const int* in_sizes, int n_in,
                              void* d_out, int out_size) {
    const float* x    = (const float*)d_in[0];      // [N, 24]
    const int*   eidx = (const int*)d_in[1];        // [2, E] int32
    const float* kv   = (const float*)d_in[2];      // [2, E]
    const float* W    = (const float*)d_in[3];      // [64, 48]
    float*       out  = (float*)d_out;

    const int N = in_sizes[0] / D_;
    const int E = in_sizes[2] / 2;

    const int blocks = (N + NPB - 1) / NPB;
    gnn_fused_kernel<<<blocks, TPB>>>(x, eidx, kv, W, out, N, E);
}